// round 1
// baseline (speedup 1.0000x reference)
#include <cuda_runtime.h>

#define NODES 62
#define BATCHG 2048
#define NN (NODES*BATCHG)          // 126976
#define HROW 384                   // x:0-128, x1:128-192, x2:192-256, x3:256-320, x4:320-384
#define PCOLS 192                  // P: c0 [0,64), c1 [64,128), c2 [128,192)  (62 real cols each)
#define LINW 512
#define LIN2 256
#define FEATK (62*256)             // 15872 padded feats K
#define EPB 496                    // edges of graph 0
#define KSPLIT 8

// ---------------- scratch (static device arrays; no allocation) ----------------
__device__ float g_H[(size_t)NN*HROW];        // layer feature buffer, 195MB
__device__ float g_P[(size_t)NN*PCOLS];       // cheb GEMM output,     97MB
__device__ float g_Wp[4][320*192];            // prepped cheb weights
__device__ float g_Wh1p[(size_t)FEATK*LINW];  // padded Wh1, 32.5MB
__device__ float g_G1p[(size_t)KSPLIT*BATCHG*LINW]; // split-K partials
__device__ float g_G1[BATCHG*LINW];
__device__ float g_G2[BATCHG*LIN2];
__device__ float g_L[62*64];
__device__ float g_L2[62*64];
__device__ float g_deg[64];
__device__ float g_mean[LINW];
__device__ float g_rstd[LINW];

// ---------------- init: H[:,0:128] = x, rest = 0 ----------------
__global__ void k_init_H(const float* __restrict__ x) {
    size_t idx = (size_t)blockIdx.x * blockDim.x + threadIdx.x;
    size_t total = (size_t)NN * (HROW/4);
    if (idx >= total) return;
    size_t n = idx / (HROW/4);
    int c4 = (int)(idx % (HROW/4));
    float4 v = make_float4(0.f,0.f,0.f,0.f);
    if (c4 < 32) v = reinterpret_cast<const float4*>(x)[n*32 + c4];
    reinterpret_cast<float4*>(g_H)[idx] = v;
}

// ---------------- build L (graph 0 topology == all graphs) ----------------
__global__ void k_deg(const int* __restrict__ row) {
    int t = threadIdx.x;
    if (t < 64) g_deg[t] = 0.f;
    __syncthreads();
    if (t < EPB) atomicAdd(&g_deg[row[t]], 1.0f);
}

__global__ void k_build_L(const int* __restrict__ row, const int* __restrict__ col) {
    int t = threadIdx.x;
    for (int i = t; i < 62*64; i += 512) { g_L[i] = 0.f; g_L2[i] = 0.f; }
    __syncthreads();
    if (t < EPB) {
        int r = row[t], c = col[t];
        float w = -rsqrtf(g_deg[r]) * rsqrtf(g_deg[c]);
        atomicAdd(&g_L[r*64 + c], w);   // equal-valued adds -> deterministic
    }
}

__global__ void k_L2() {
    int t = blockIdx.x*256 + threadIdx.x;
    if (t >= 62*64) return;
    int i = t / 64, j = t % 64;
    float s = 0.f;
    if (j < 62)
        for (int m = 0; m < 62; m++) s += g_L[i*64+m] * g_L[m*64+j];
    g_L2[t] = s;
}

// ---------------- weight prep ----------------
// Wp[dpad][192]: cols [0,62)=W0-W2, [64,126)=W1, [128,190)=2*W2, pads zero.
// padded row r -> real feature row rr (x:0-127 direct; chunks of 64 -> 62 real).
__global__ void k_prepW(const float* __restrict__ W, int dreal, int dpad,
                        float* __restrict__ Wp) {
    int t = blockIdx.x*256 + threadIdx.x;
    if (t >= dpad*192) return;
    int r = t / 192, c = t % 192;
    int ch = c >> 6, j = c & 63;
    float val = 0.f;
    int rr = -1;
    if (r < 128) rr = r;
    else { int q = r - 128; int chunk = q >> 6, w = q & 63; if (w < 62) rr = 128 + chunk*62 + w; }
    if (rr >= 0 && rr < dreal && j < 62) {
        const float* W0 = W;
        const float* W1 = W + (size_t)dreal*62;
        const float* W2 = W + (size_t)2*dreal*62;
        if (ch == 0)      val = W0[rr*62+j] - W2[rr*62+j];
        else if (ch == 1) val = W1[rr*62+j];
        else              val = 2.f * W2[rr*62+j];
    }
    Wp[t] = val;
}

// Wh1p[15872][512] from Wh1[15376][512]: padded k -> (node, chunk, w)
__global__ void k_prepWh1(const float* __restrict__ Wh1) {
    int t = blockIdx.x*256 + threadIdx.x;
    if (t >= FEATK*LINW) return;
    int r = t / LINW, c = t % LINW;
    int node = r >> 8, cc = r & 255;
    int ch = cc >> 6, w = cc & 63;
    float val = 0.f;
    if (w < 62) val = Wh1[((size_t)(node*248 + ch*62 + w))*LINW + c];
    g_Wh1p[t] = val;
}

// ---------------- generic fp32 GEMM: 64x64 tile, BK=16, 256 thr, 4x4/thread ----------
// FEATS mode: A element (m,k) read from g_H viewed as [2048, 62*384] with
// offset (k>>8)*384 + 128 + (k&255)  (reads feats in place, pads are zero).
template<bool FEATS>
__global__ void gemm_k(const float* __restrict__ A, const float* __restrict__ B,
                       float* __restrict__ C, int M, int N, int K,
                       int lda, int ldb, int ldc, int kparts, size_t cstride)
{
    __shared__ float As[16][68];
    __shared__ float Bs[16][64];
    int t = threadIdx.x;
    int m0 = blockIdx.y * 64, n0 = blockIdx.x * 64;
    int kper = K / kparts;
    int kbeg = blockIdx.z * kper, kend = kbeg + kper;
    float* Cz = C + (size_t)blockIdx.z * cstride;
    int ty = t >> 4, tx = t & 15;
    int am = t >> 2, ak = (t & 3) * 4;
    int bk = t >> 4, bn = (t & 15) * 4;
    float acc[4][4];
#pragma unroll
    for (int i = 0; i < 4; i++)
#pragma unroll
        for (int j = 0; j < 4; j++) acc[i][j] = 0.f;

    for (int k0 = kbeg; k0 < kend; k0 += 16) {
        size_t aoff;
        if (FEATS) {
            int kk = k0 + ak;
            aoff = (size_t)(m0+am)*23808 + (size_t)((kk >> 8)*384 + 128 + (kk & 255));
        } else {
            aoff = (size_t)(m0+am)*lda + (k0 + ak);
        }
        float4 av = *reinterpret_cast<const float4*>(A + aoff);
        As[ak+0][am] = av.x; As[ak+1][am] = av.y; As[ak+2][am] = av.z; As[ak+3][am] = av.w;
        float4 bv = *reinterpret_cast<const float4*>(B + (size_t)(k0+bk)*ldb + n0 + bn);
        *reinterpret_cast<float4*>(&Bs[bk][bn]) = bv;
        __syncthreads();
#pragma unroll
        for (int k = 0; k < 16; k++) {
            float4 a4 = *reinterpret_cast<const float4*>(&As[k][ty*4]);
            float4 b4 = *reinterpret_cast<const float4*>(&Bs[k][tx*4]);
            float a[4] = {a4.x, a4.y, a4.z, a4.w};
            float b[4] = {b4.x, b4.y, b4.z, b4.w};
#pragma unroll
            for (int i = 0; i < 4; i++)
#pragma unroll
                for (int j = 0; j < 4; j++) acc[i][j] += a[i]*b[j];
        }
        __syncthreads();
    }
#pragma unroll
    for (int i = 0; i < 4; i++) {
        float4 v = make_float4(acc[i][0], acc[i][1], acc[i][2], acc[i][3]);
        *reinterpret_cast<float4*>(Cz + (size_t)(m0 + ty*4 + i)*ldc + n0 + tx*4) = v;
    }
}

__global__ void k_reduceK() {
    int t = blockIdx.x*256 + threadIdx.x;
    if (t >= BATCHG*LINW) return;
    float s = 0.f;
#pragma unroll
    for (int p = 0; p < KSPLIT; p++) s += g_G1p[(size_t)p*BATCHG*LINW + t];
    g_G1[t] = s;
}

// ---------------- combine: out = P0 + L@P1 + L2@P2, +bias, relu -> H chunk ----------
__global__ void k_combine(const float* __restrict__ bias, int cbase) {
    __shared__ float Ps[62][192];
    int b = blockIdx.x;
    int t = threadIdx.x;
    const float* Pg = g_P + (size_t)b * 62 * 192;
    for (int idx = t; idx < 62*48; idx += 256) {
        int m = idx / 48, q = idx % 48;
        *reinterpret_cast<float4*>(&Ps[m][q*4]) =
            *reinterpret_cast<const float4*>(Pg + m*192 + q*4);
    }
    __syncthreads();
    int j4 = t & 15;  int jj = j4 * 4;
    int i0 = t >> 4;
    float* Hb = g_H + (size_t)b * 62 * HROW + cbase;
    for (int ii = 0; ii < 4; ii++) {
        int i = i0 + ii*16;
        if (i >= 62) break;
        float4 acc = *reinterpret_cast<float4*>(&Ps[i][jj]);   // identity term (c0)
#pragma unroll 2
        for (int m = 0; m < 62; m++) {
            float l1 = __ldg(&g_L [i*64 + m]);
            float l2 = __ldg(&g_L2[i*64 + m]);
            float4 p1 = *reinterpret_cast<float4*>(&Ps[m][ 64 + jj]);
            float4 p2 = *reinterpret_cast<float4*>(&Ps[m][128 + jj]);
            acc.x += l1*p1.x + l2*p2.x;
            acc.y += l1*p1.y + l2*p2.y;
            acc.z += l1*p1.z + l2*p2.z;
            acc.w += l1*p1.w + l2*p2.w;
        }
        float4 o;
        o.x = (jj+0 < 62) ? fmaxf(acc.x + bias[jj+0], 0.f) : 0.f;
        o.y = (jj+1 < 62) ? fmaxf(acc.y + bias[jj+1], 0.f) : 0.f;
        o.z = (jj+2 < 62) ? fmaxf(acc.z + bias[jj+2], 0.f) : 0.f;
        o.w = (jj+3 < 62) ? fmaxf(acc.w + bias[jj+3], 0.f) : 0.f;
        *reinterpret_cast<float4*>(Hb + (size_t)i*HROW + jj) = o;
    }
}

// ---------------- batchnorm ----------------
__global__ void k_bnstats(const float* __restrict__ X, int ld) {
    int c = blockIdx.x;
    int t = threadIdx.x;
    float s = 0.f, sq = 0.f;
    for (int r = t; r < BATCHG; r += 256) {
        float v = X[(size_t)r*ld + c];
        s += v; sq += v*v;
    }
    __shared__ float sh[256], sh2[256];
    sh[t] = s; sh2[t] = sq; __syncthreads();
    for (int o = 128; o > 0; o >>= 1) {
        if (t < o) { sh[t] += sh[t+o]; sh2[t] += sh2[t+o]; }
        __syncthreads();
    }
    if (t == 0) {
        float m = sh[0] * (1.f/BATCHG);
        float v = sh2[0] * (1.f/BATCHG) - m*m;
        g_mean[c] = m;
        g_rstd[c] = rsqrtf(v + 1e-5f);
    }
}

__global__ void k_bnrelu(float* __restrict__ X, int nc,
                         const float* __restrict__ gamma, const float* __restrict__ beta) {
    int idx = blockIdx.x*256 + threadIdx.x;
    if (idx >= BATCHG*nc) return;
    int c = idx % nc;
    float v = X[idx];
    v = (v - g_mean[c]) * g_rstd[c] * gamma[c] + beta[c];
    X[idx] = fmaxf(v, 0.f);
}

// ---------------- final logits + softmax ----------------
__global__ void k_final(const float* __restrict__ Wh3, const float* __restrict__ bh3,
                        float* __restrict__ out) {
    int r = blockIdx.x*256 + threadIdx.x;
    if (r >= BATCHG) return;
    const float* h = g_G2 + (size_t)r * LIN2;
    float a0 = bh3[0], a1 = bh3[1], a2 = bh3[2];
    for (int k = 0; k < LIN2; k++) {
        float v = h[k];
        a0 += v * Wh3[k*3+0];
        a1 += v * Wh3[k*3+1];
        a2 += v * Wh3[k*3+2];
    }
    float mx = fmaxf(a0, fmaxf(a1, a2));
    float e0 = expf(a0-mx), e1 = expf(a1-mx), e2 = expf(a2-mx);
    float inv = 1.f / (e0+e1+e2);
    out[r*3+0] = e0*inv; out[r*3+1] = e1*inv; out[r*3+2] = e2*inv;
}

// ---------------- launch ----------------
extern "C" void kernel_launch(void* const* d_in, const int* in_sizes, int n_in,
                              void* d_out, int out_size) {
    const float* x   = (const float*)d_in[0];
    const int*   ei  = (const int*)  d_in[1];
    const float* W[4]  = {(const float*)d_in[2], (const float*)d_in[4],
                          (const float*)d_in[6], (const float*)d_in[8]};
    const float* bb[4] = {(const float*)d_in[3], (const float*)d_in[5],
                          (const float*)d_in[7], (const float*)d_in[9]};
    const float* Wh1 = (const float*)d_in[10];
    const float* g1  = (const float*)d_in[12];
    const float* be1 = (const float*)d_in[13];
    const float* Wh2 = (const float*)d_in[14];
    const float* g2  = (const float*)d_in[16];
    const float* be2 = (const float*)d_in[17];
    const float* Wh3 = (const float*)d_in[18];
    const float* bh3 = (const float*)d_in[19];
    float* out = (float*)d_out;

    int E = in_sizes[1] / 2;
    const int* row = ei;
    const int* col = ei + E;

    float *hH, *hP, *hWp, *hWh1p, *hG1p, *hG1, *hG2;
    cudaGetSymbolAddress((void**)&hH,    g_H);
    cudaGetSymbolAddress((void**)&hP,    g_P);
    cudaGetSymbolAddress((void**)&hWp,   g_Wp);
    cudaGetSymbolAddress((void**)&hWh1p, g_Wh1p);
    cudaGetSymbolAddress((void**)&hG1p,  g_G1p);
    cudaGetSymbolAddress((void**)&hG1,   g_G1);
    cudaGetSymbolAddress((void**)&hG2,   g_G2);

    const int DPAD[4]  = {128, 192, 256, 320};
    const int DREAL[4] = {128, 190, 252, 314};

    // init + L
    {
        size_t total = (size_t)NN * (HROW/4);
        k_init_H<<<(unsigned)((total + 255)/256), 256>>>(x);
    }
    k_deg<<<1, 512>>>(row);
    k_build_L<<<1, 512>>>(row, col);
    k_L2<<<16, 256>>>();

    // weight prep
    for (int i = 0; i < 4; i++) {
        int n = DPAD[i]*192;
        k_prepW<<<(n+255)/256, 256>>>(W[i], DREAL[i], DPAD[i], hWp + (size_t)i*320*192);
    }
    k_prepWh1<<<(FEATK*LINW + 255)/256, 256>>>(Wh1);

    // 4 cheb layers
    for (int i = 0; i < 4; i++) {
        gemm_k<false><<<dim3(3, NN/64, 1), 256>>>(
            hH, hWp + (size_t)i*320*192, hP,
            NN, 192, DPAD[i], HROW, 192, 192, 1, 0);
        k_combine<<<BATCHG, 256>>>(bb[i], 128 + 64*i);
    }

    // MLP head
    gemm_k<true><<<dim3(LINW/64, BATCHG/64, KSPLIT), 256>>>(
        hH, hWh1p, hG1p,
        BATCHG, LINW, FEATK, 0, LINW, LINW, KSPLIT, (size_t)BATCHG*LINW);
    k_reduceK<<<(BATCHG*LINW + 255)/256, 256>>>();
    k_bnstats<<<LINW, 256>>>(hG1, LINW);
    k_bnrelu<<<(BATCHG*LINW + 255)/256, 256>>>(hG1, LINW, g1, be1);

    gemm_k<false><<<dim3(LIN2/64, BATCHG/64, 1), 256>>>(
        hG1, Wh2, hG2, BATCHG, LIN2, LINW, LINW, LIN2, LIN2, 1, 0);
    k_bnstats<<<LIN2, 256>>>(hG2, LIN2);
    k_bnrelu<<<(BATCHG*LIN2 + 255)/256, 256>>>(hG2, LIN2, g2, be2);

    k_final<<<(BATCHG + 255)/256, 256>>>(Wh3, bh3, out);
}